// round 1
// baseline (speedup 1.0000x reference)
#include <cuda_runtime.h>
#include <math.h>
#include <stdint.h>

#define BN_ 8
#define L_ 2048
#define D_ 1024

// Scratch: E = A @ B^T per batch  (8 * 2048 * 2048 floats = 134 MB)
__device__ float g_E[(size_t)BN_ * L_ * L_];
__device__ float g_rmax[BN_ * L_];
__device__ float g_rsumInv[BN_ * L_];
__device__ float g_cmax[BN_ * L_];
__device__ float g_csumInv[BN_ * L_];

#define NEG_INF __int_as_float(0xff800000)

// ---------------------------------------------------------------------------
// Kernel 1: E[b,i,j] = sum_d A[b,i,d] * B[b,j,d]   (NT GEMM, M=N=2048, K=1024)
// 128x128 tile, BK=8, 256 threads, 8x8 per-thread microtile.
// ---------------------------------------------------------------------------
__global__ __launch_bounds__(256) void k_gemm_e(const float* __restrict__ A,
                                                const float* __restrict__ B) {
    __shared__ float As[8][128];
    __shared__ float Bs[8][128];
    const int b  = blockIdx.z;
    const int i0 = blockIdx.y * 128;
    const int j0 = blockIdx.x * 128;
    const float* Ab = A + (size_t)b * L_ * D_;
    const float* Bb = B + (size_t)b * L_ * D_;
    float* Eb = g_E + (size_t)b * L_ * L_;

    const int tid = threadIdx.x;
    const int tx = tid & 15;       // 0..15 -> j microtile
    const int ty = tid >> 4;       // 0..15 -> i microtile
    const int lRow = tid >> 1;     // 0..127
    const int lCol = (tid & 1) * 4;

    float acc[8][8];
    #pragma unroll
    for (int m = 0; m < 8; m++)
        #pragma unroll
        for (int n = 0; n < 8; n++) acc[m][n] = 0.f;

    for (int k0 = 0; k0 < D_; k0 += 8) {
        float4 av = *(const float4*)(Ab + (size_t)(i0 + lRow) * D_ + k0 + lCol);
        float4 bv = *(const float4*)(Bb + (size_t)(j0 + lRow) * D_ + k0 + lCol);
        As[lCol + 0][lRow] = av.x; As[lCol + 1][lRow] = av.y;
        As[lCol + 2][lRow] = av.z; As[lCol + 3][lRow] = av.w;
        Bs[lCol + 0][lRow] = bv.x; Bs[lCol + 1][lRow] = bv.y;
        Bs[lCol + 2][lRow] = bv.z; Bs[lCol + 3][lRow] = bv.w;
        __syncthreads();
        #pragma unroll
        for (int k = 0; k < 8; k++) {
            float4 a0 = *(const float4*)(&As[k][ty * 8]);
            float4 a1 = *(const float4*)(&As[k][ty * 8 + 4]);
            float4 b0 = *(const float4*)(&Bs[k][tx * 8]);
            float4 b1 = *(const float4*)(&Bs[k][tx * 8 + 4]);
            float ra[8] = {a0.x, a0.y, a0.z, a0.w, a1.x, a1.y, a1.z, a1.w};
            float rb[8] = {b0.x, b0.y, b0.z, b0.w, b1.x, b1.y, b1.z, b1.w};
            #pragma unroll
            for (int m = 0; m < 8; m++)
                #pragma unroll
                for (int n = 0; n < 8; n++) acc[m][n] = fmaf(ra[m], rb[n], acc[m][n]);
        }
        __syncthreads();
    }

    #pragma unroll
    for (int m = 0; m < 8; m++) {
        float* dst = Eb + (size_t)(i0 + ty * 8 + m) * L_ + j0 + tx * 8;
        *(float4*)(dst)     = make_float4(acc[m][0], acc[m][1], acc[m][2], acc[m][3]);
        *(float4*)(dst + 4) = make_float4(acc[m][4], acc[m][5], acc[m][6], acc[m][7]);
    }
}

// ---------------------------------------------------------------------------
// Row stats: max & 1/sumexp over j for each (b, i).  One block per row.
// ---------------------------------------------------------------------------
__global__ __launch_bounds__(256) void k_rowstats() {
    const int b = blockIdx.y, r = blockIdx.x;
    const float* row = g_E + (size_t)(b * L_ + r) * L_;
    const int tid = threadIdx.x;
    __shared__ float red[256];

    float m = NEG_INF;
    for (int j = tid; j < L_; j += 256) m = fmaxf(m, row[j]);
    red[tid] = m; __syncthreads();
    for (int s = 128; s >= 1; s >>= 1) {
        if (tid < s) red[tid] = fmaxf(red[tid], red[tid + s]);
        __syncthreads();
    }
    const float M = red[0];
    __syncthreads();

    float sum = 0.f;
    for (int j = tid; j < L_; j += 256) sum += __expf(row[j] - M);
    red[tid] = sum; __syncthreads();
    for (int s = 128; s >= 1; s >>= 1) {
        if (tid < s) red[tid] += red[tid + s];
        __syncthreads();
    }
    if (tid == 0) {
        g_rmax[b * L_ + r]    = M;
        g_rsumInv[b * L_ + r] = 1.0f / red[0];
    }
}

// ---------------------------------------------------------------------------
// Col stats: max & 1/sumexp over i for each (b, j). Thread per column.
// ---------------------------------------------------------------------------
__global__ __launch_bounds__(256) void k_colstats() {
    const int b = blockIdx.y;
    const int j = blockIdx.x * 256 + threadIdx.x;
    const float* base = g_E + (size_t)b * L_ * L_ + j;

    float m = NEG_INF;
    #pragma unroll 8
    for (int i = 0; i < L_; i++) m = fmaxf(m, base[(size_t)i * L_]);
    float sum = 0.f;
    #pragma unroll 8
    for (int i = 0; i < L_; i++) sum += __expf(base[(size_t)i * L_] - m);

    g_cmax[b * L_ + j]    = m;
    g_csumInv[b * L_ + j] = 1.0f / sum;
}

// ---------------------------------------------------------------------------
// a_tilda[b,i,d] = sum_j softmax_row(E)[i,j] * B[b,j,d]
// M=i(2048), N=d(1024), K=j(2048). Exp applied while staging the E tile.
// ---------------------------------------------------------------------------
__global__ __launch_bounds__(256) void k_atilda(const float* __restrict__ B,
                                                float* __restrict__ out) {
    __shared__ float Ps[8][128];
    __shared__ float Bs[8][128];
    const int b  = blockIdx.z;
    const int i0 = blockIdx.y * 128;
    const int d0 = blockIdx.x * 128;
    const float* Eb = g_E + (size_t)b * L_ * L_;
    const float* Bb = B + (size_t)b * L_ * D_;

    const int tid = threadIdx.x;
    const int tx = tid & 15, ty = tid >> 4;
    const int pRow = tid >> 1;          // i within tile
    const int pCol = (tid & 1) * 4;     // j within k-slab
    const int bRow = tid >> 5;          // j within k-slab (0..7)
    const int bCol = (tid & 31) * 4;    // d within tile

    const float rm = g_rmax[b * L_ + i0 + pRow];
    const float ri = g_rsumInv[b * L_ + i0 + pRow];

    float acc[8][8];
    #pragma unroll
    for (int m = 0; m < 8; m++)
        #pragma unroll
        for (int n = 0; n < 8; n++) acc[m][n] = 0.f;

    for (int j0 = 0; j0 < L_; j0 += 8) {
        float4 ev = *(const float4*)(Eb + (size_t)(i0 + pRow) * L_ + j0 + pCol);
        Ps[pCol + 0][pRow] = __expf(ev.x - rm) * ri;
        Ps[pCol + 1][pRow] = __expf(ev.y - rm) * ri;
        Ps[pCol + 2][pRow] = __expf(ev.z - rm) * ri;
        Ps[pCol + 3][pRow] = __expf(ev.w - rm) * ri;
        *(float4*)(&Bs[bRow][bCol]) =
            *(const float4*)(Bb + (size_t)(j0 + bRow) * D_ + d0 + bCol);
        __syncthreads();
        #pragma unroll
        for (int k = 0; k < 8; k++) {
            float4 a0 = *(const float4*)(&Ps[k][ty * 8]);
            float4 a1 = *(const float4*)(&Ps[k][ty * 8 + 4]);
            float4 b0 = *(const float4*)(&Bs[k][tx * 8]);
            float4 b1 = *(const float4*)(&Bs[k][tx * 8 + 4]);
            float ra[8] = {a0.x, a0.y, a0.z, a0.w, a1.x, a1.y, a1.z, a1.w};
            float rb[8] = {b0.x, b0.y, b0.z, b0.w, b1.x, b1.y, b1.z, b1.w};
            #pragma unroll
            for (int m = 0; m < 8; m++)
                #pragma unroll
                for (int n = 0; n < 8; n++) acc[m][n] = fmaf(ra[m], rb[n], acc[m][n]);
        }
        __syncthreads();
    }

    #pragma unroll
    for (int m = 0; m < 8; m++) {
        float* dst = out + (size_t)(b * L_ + i0 + ty * 8 + m) * D_ + d0 + tx * 8;
        *(float4*)(dst)     = make_float4(acc[m][0], acc[m][1], acc[m][2], acc[m][3]);
        *(float4*)(dst + 4) = make_float4(acc[m][4], acc[m][5], acc[m][6], acc[m][7]);
    }
}

// ---------------------------------------------------------------------------
// b_tilda[b,j,d] = sum_i softmax_col(E)[i,j] * A[b,i,d]
// M=j(2048), N=d(1024), K=i(2048). E tile is naturally [k=i][j] — no transpose.
// ---------------------------------------------------------------------------
__global__ __launch_bounds__(256) void k_btilda(const float* __restrict__ A,
                                                float* __restrict__ out) {
    __shared__ float Qs[8][128];
    __shared__ float As_[8][128];
    const int b  = blockIdx.z;
    const int j0 = blockIdx.y * 128;
    const int d0 = blockIdx.x * 128;
    const float* Eb = g_E + (size_t)b * L_ * L_;
    const float* Ab = A + (size_t)b * L_ * D_;

    const int tid = threadIdx.x;
    const int tx = tid & 15, ty = tid >> 4;
    const int eRow = tid >> 5;          // i within k-slab (0..7)
    const int eCol = (tid & 31) * 4;    // j within tile

    const float4 cm = *(const float4*)(g_cmax + b * L_ + j0 + eCol);
    const float4 ci = *(const float4*)(g_csumInv + b * L_ + j0 + eCol);

    float acc[8][8];
    #pragma unroll
    for (int m = 0; m < 8; m++)
        #pragma unroll
        for (int n = 0; n < 8; n++) acc[m][n] = 0.f;

    for (int i0 = 0; i0 < L_; i0 += 8) {
        float4 ev = *(const float4*)(Eb + (size_t)(i0 + eRow) * L_ + j0 + eCol);
        float4 q;
        q.x = __expf(ev.x - cm.x) * ci.x;
        q.y = __expf(ev.y - cm.y) * ci.y;
        q.z = __expf(ev.z - cm.z) * ci.z;
        q.w = __expf(ev.w - cm.w) * ci.w;
        *(float4*)(&Qs[eRow][eCol]) = q;
        *(float4*)(&As_[eRow][eCol]) =
            *(const float4*)(Ab + (size_t)(i0 + eRow) * D_ + d0 + eCol);
        __syncthreads();
        #pragma unroll
        for (int k = 0; k < 8; k++) {
            float4 a0 = *(const float4*)(&Qs[k][ty * 8]);
            float4 a1 = *(const float4*)(&Qs[k][ty * 8 + 4]);
            float4 b0 = *(const float4*)(&As_[k][tx * 8]);
            float4 b1 = *(const float4*)(&As_[k][tx * 8 + 4]);
            float ra[8] = {a0.x, a0.y, a0.z, a0.w, a1.x, a1.y, a1.z, a1.w};
            float rb[8] = {b0.x, b0.y, b0.z, b0.w, b1.x, b1.y, b1.z, b1.w};
            #pragma unroll
            for (int m = 0; m < 8; m++)
                #pragma unroll
                for (int n = 0; n < 8; n++) acc[m][n] = fmaf(ra[m], rb[n], acc[m][n]);
        }
        __syncthreads();
    }

    #pragma unroll
    for (int m = 0; m < 8; m++) {
        float* dst = out + (size_t)(b * L_ + j0 + ty * 8 + m) * D_ + d0 + tx * 8;
        *(float4*)(dst)     = make_float4(acc[m][0], acc[m][1], acc[m][2], acc[m][3]);
        *(float4*)(dst + 4) = make_float4(acc[m][4], acc[m][5], acc[m][6], acc[m][7]);
    }
}

// ---------------------------------------------------------------------------
extern "C" void kernel_launch(void* const* d_in, const int* in_sizes, int n_in,
                              void* d_out, int out_size) {
    const float* A = (const float*)d_in[0];
    const float* B = (const float*)d_in[1];
    float* out = (float*)d_out;
    float* a_tilda = out;
    float* b_tilda = out + (size_t)BN_ * L_ * D_;

    dim3 gE(L_ / 128, L_ / 128, BN_);      // (16,16,8)
    k_gemm_e<<<gE, 256>>>(A, B);

    k_rowstats<<<dim3(L_, BN_), 256>>>();
    k_colstats<<<dim3(L_ / 256, BN_), 256>>>();

    dim3 gAT(D_ / 128, L_ / 128, BN_);     // (8,16,8)
    k_atilda<<<gAT, 256>>>(B, a_tilda);
    k_btilda<<<gAT, 256>>>(A, b_tilda);
}

// round 3
// speedup vs baseline: 2.8303x; 2.8303x over previous
#include <cuda_runtime.h>
#include <math.h>
#include <stdint.h>

#define BN_ 8
#define L_ 2048
#define D_ 1024

// Scratch
__device__ float g_E[(size_t)BN_ * L_ * L_];
__device__ float g_rmax[BN_ * L_];
__device__ float g_rsumInv[BN_ * L_];
__device__ float g_cmax[BN_ * L_];
__device__ float g_csumInv[BN_ * L_];

#define NEG_INF __int_as_float(0xff800000)

// ---------------------------------------------------------------------------
// Helpers (non-arch-suffixed PTX only: mma.sync tf32 + cp.async)
// ---------------------------------------------------------------------------
static __device__ __forceinline__ uint32_t smem_u32(const void* p) {
    uint32_t a;
    asm("{ .reg .u64 t; cvta.to.shared.u64 t, %1; cvt.u32.u64 %0, t; }"
        : "=r"(a) : "l"(p));
    return a;
}
static __device__ __forceinline__ uint32_t cvt_tf32(float x) {
    uint32_t h;
    asm("cvt.rna.tf32.f32 %0, %1;" : "=r"(h) : "f"(x));
    return h;
}
static __device__ __forceinline__ void split_tf32(float x, uint32_t& h, uint32_t& l) {
    h = cvt_tf32(x);
    l = __float_as_uint(x - __uint_as_float(h));
}
static __device__ __forceinline__ void mma8(float c[4], const uint32_t a[4],
                                            const uint32_t b[2]) {
    asm volatile(
        "mma.sync.aligned.m16n8k8.row.col.f32.tf32.tf32.f32 "
        "{%0,%1,%2,%3},{%4,%5,%6,%7},{%8,%9},{%0,%1,%2,%3};"
        : "+f"(c[0]), "+f"(c[1]), "+f"(c[2]), "+f"(c[3])
        : "r"(a[0]), "r"(a[1]), "r"(a[2]), "r"(a[3]), "r"(b[0]), "r"(b[1]));
}
static __device__ __forceinline__ void cpa16(uint32_t dst, const void* src) {
    asm volatile("cp.async.cg.shared.global [%0], [%1], 16;" :: "r"(dst), "l"(src));
}
#define CP_COMMIT() asm volatile("cp.async.commit_group;" ::: "memory")
#define CP_WAIT1()  asm volatile("cp.async.wait_group 1;" ::: "memory")
#define CP_WAIT0()  asm volatile("cp.async.wait_group 0;" ::: "memory")

// ---------------------------------------------------------------------------
// E = A @ B^T via 3xTF32.  128x128 tile, BK=32, 8 warps (4m x 2n).
// SMEM: raw fp32 tiles As[128][36], Bs[128][36], double buffered (72KB).
// ---------------------------------------------------------------------------
#define EPAD 36
#define EBUF (128 * EPAD)
__global__ __launch_bounds__(256, 1) void k_gemm_e(const float* __restrict__ A,
                                                   const float* __restrict__ B) {
    extern __shared__ float sm[];
    float* smA = sm;                 // 2 * EBUF
    float* smB = sm + 2 * EBUF;      // 2 * EBUF
    const uint32_t sA = smem_u32(smA), sB = smem_u32(smB);
    const int tid = threadIdx.x, lane = tid & 31, wid = tid >> 5;
    const int wm = wid & 3, wn = wid >> 2;
    const int q = lane >> 2, r = lane & 3;
    const int b = blockIdx.z, i0 = blockIdx.y * 128, j0 = blockIdx.x * 128;
    const float* Ab = A + ((size_t)b * L_ + i0) * D_;
    const float* Bb = B + ((size_t)b * L_ + j0) * D_;

    float acc[2][8][4];
    #pragma unroll
    for (int mt = 0; mt < 2; mt++)
        #pragma unroll
        for (int nt = 0; nt < 8; nt++)
            #pragma unroll
            for (int e = 0; e < 4; e++) acc[mt][nt][e] = 0.f;

    // stage chunk c into buffer c&1
    #define STAGE_E_(c)                                                          \
        do {                                                                     \
            const int _buf = (c) & 1, _k0 = (c) * 32;                            \
            _Pragma("unroll")                                                    \
            for (int t = 0; t < 4; t++) {                                        \
                int idx = t * 256 + tid;                                         \
                int row = idx >> 3, ch = idx & 7;                                \
                cpa16(sA + (uint32_t)(_buf * EBUF + row * EPAD + ch * 4) * 4u,   \
                      Ab + (size_t)row * D_ + _k0 + ch * 4);                     \
                cpa16(sB + (uint32_t)(_buf * EBUF + row * EPAD + ch * 4) * 4u,   \
                      Bb + (size_t)row * D_ + _k0 + ch * 4);                     \
            }                                                                    \
            CP_COMMIT();                                                         \
        } while (0)

    STAGE_E_(0);
    for (int c = 0; c < 32; c++) {
        if (c + 1 < 32) { STAGE_E_(c + 1); CP_WAIT1(); }
        else            { CP_WAIT0(); }
        __syncthreads();
        const float* As_ = smA + (c & 1) * EBUF;
        const float* Bs_ = smB + (c & 1) * EBUF;
        #pragma unroll
        for (int ks = 0; ks < 4; ks++) {
            const int kb = ks * 8;
            uint32_t ah[2][4], al[2][4], bh[8][2], bl[8][2];
            #pragma unroll
            for (int mt = 0; mt < 2; mt++) {
                const int rb = wm * 32 + mt * 16;
                float x0 = As_[(rb + q) * EPAD + kb + r];
                float x1 = As_[(rb + q + 8) * EPAD + kb + r];
                float x2 = As_[(rb + q) * EPAD + kb + r + 4];
                float x3 = As_[(rb + q + 8) * EPAD + kb + r + 4];
                split_tf32(x0, ah[mt][0], al[mt][0]);
                split_tf32(x1, ah[mt][1], al[mt][1]);
                split_tf32(x2, ah[mt][2], al[mt][2]);
                split_tf32(x3, ah[mt][3], al[mt][3]);
            }
            #pragma unroll
            for (int nt = 0; nt < 8; nt++) {
                const int nb = wn * 64 + nt * 8;
                float y0 = Bs_[(nb + q) * EPAD + kb + r];
                float y1 = Bs_[(nb + q) * EPAD + kb + r + 4];
                split_tf32(y0, bh[nt][0], bl[nt][0]);
                split_tf32(y1, bh[nt][1], bl[nt][1]);
            }
            #pragma unroll
            for (int mt = 0; mt < 2; mt++)
                #pragma unroll
                for (int nt = 0; nt < 8; nt++) {
                    mma8(acc[mt][nt], al[mt], bh[nt]);
                    mma8(acc[mt][nt], ah[mt], bl[nt]);
                    mma8(acc[mt][nt], ah[mt], bh[nt]);
                }
        }
        __syncthreads();
    }

    float* Eb = g_E + ((size_t)b * L_ + i0) * L_ + j0;
    #pragma unroll
    for (int mt = 0; mt < 2; mt++)
        #pragma unroll
        for (int nt = 0; nt < 8; nt++) {
            int row = wm * 32 + mt * 16 + q;
            int col = wn * 64 + nt * 8 + r * 2;
            *(float2*)(Eb + (size_t)row * L_ + col) =
                make_float2(acc[mt][nt][0], acc[mt][nt][1]);
            *(float2*)(Eb + (size_t)(row + 8) * L_ + col) =
                make_float2(acc[mt][nt][2], acc[mt][nt][3]);
        }
    #undef STAGE_E_
}

// ---------------------------------------------------------------------------
// Row stats
// ---------------------------------------------------------------------------
__global__ __launch_bounds__(256) void k_rowstats() {
    const int b = blockIdx.y, rrow = blockIdx.x;
    const float* row = g_E + (size_t)(b * L_ + rrow) * L_;
    const int tid = threadIdx.x;
    __shared__ float red[256];

    float m = NEG_INF;
    for (int j = tid * 4; j < L_; j += 1024) {
        float4 v = *(const float4*)(row + j);
        m = fmaxf(m, fmaxf(fmaxf(v.x, v.y), fmaxf(v.z, v.w)));
    }
    red[tid] = m; __syncthreads();
    for (int s = 128; s >= 1; s >>= 1) {
        if (tid < s) red[tid] = fmaxf(red[tid], red[tid + s]);
        __syncthreads();
    }
    const float M = red[0];
    __syncthreads();

    float sum = 0.f;
    for (int j = tid * 4; j < L_; j += 1024) {
        float4 v = *(const float4*)(row + j);
        sum += __expf(v.x - M) + __expf(v.y - M) + __expf(v.z - M) + __expf(v.w - M);
    }
    red[tid] = sum; __syncthreads();
    for (int s = 128; s >= 1; s >>= 1) {
        if (tid < s) red[tid] += red[tid + s];
        __syncthreads();
    }
    if (tid == 0) {
        g_rmax[b * L_ + rrow] = M;
        g_rsumInv[b * L_ + rrow] = 1.0f / red[0];
    }
}

// ---------------------------------------------------------------------------
// Col stats: online softmax, 32 cols/block, 8 i-slices -> 512 blocks/batch-set
// ---------------------------------------------------------------------------
__global__ __launch_bounds__(256) void k_colstats() {
    const int b = blockIdx.y;
    const int jt = threadIdx.x & 31;
    const int isl = threadIdx.x >> 5;
    const int j = blockIdx.x * 32 + jt;
    const float* base = g_E + (size_t)b * L_ * L_ + j;

    float m = NEG_INF, s = 0.f;
    const int ibeg = isl * 256, iend = ibeg + 256;
    for (int i = ibeg; i < iend; i++) {
        float x = base[(size_t)i * L_];
        if (x <= m) {
            s += __expf(x - m);
        } else {
            s = s * __expf(m - x) + 1.f;
            m = x;
        }
    }
    __shared__ float ms[8][32], ss[8][32];
    ms[isl][jt] = m; ss[isl][jt] = s;
    __syncthreads();
    if (isl == 0) {
        float M = m, S = s;
        #pragma unroll
        for (int k = 1; k < 8; k++) {
            float mk = ms[k][jt], sk = ss[k][jt];
            if (mk <= M) {
                S += sk * __expf(mk - M);
            } else {
                S = S * __expf(M - mk) + sk;
                M = mk;
            }
        }
        g_cmax[b * L_ + j] = M;
        g_csumInv[b * L_ + j] = 1.0f / S;
    }
}

// ---------------------------------------------------------------------------
// a_tilda[i,d] = sum_j P[i,j] * B[j,d].  M=i, N=d, K=j.
// Ps[128][36] ([m][k], exp applied), Bs2[32][136] ([k][n] raw fp32).
// P single tf32; B split hi/lo (2 mma terms).
// ---------------------------------------------------------------------------
#define PPAD 36
#define PBUF (128 * PPAD)
#define NPAD 136
#define NBUF (32 * NPAD)
__global__ __launch_bounds__(256, 1) void k_atilda(const float* __restrict__ B,
                                                   float* __restrict__ out) {
    extern __shared__ float sm[];
    float* Ps = sm;                       // 2 * PBUF
    float* Bs = sm + 2 * PBUF;            // 2 * NBUF
    float* rm_s = sm + 2 * PBUF + 2 * NBUF;
    float* ri_s = rm_s + 128;
    const int tid = threadIdx.x, lane = tid & 31, wid = tid >> 5;
    const int wm = wid & 3, wn = wid >> 2;
    const int q = lane >> 2, r = lane & 3;
    const int b = blockIdx.z, i0 = blockIdx.y * 128, d0 = blockIdx.x * 128;
    const float* Eb = g_E + (size_t)b * L_ * L_;
    const float* Bb = B + (size_t)b * L_ * D_;

    if (tid < 128) {
        rm_s[tid] = g_rmax[b * L_ + i0 + tid];
        ri_s[tid] = g_rsumInv[b * L_ + i0 + tid];
    }
    __syncthreads();

    float acc[2][8][4];
    #pragma unroll
    for (int mt = 0; mt < 2; mt++)
        #pragma unroll
        for (int nt = 0; nt < 8; nt++)
            #pragma unroll
            for (int e = 0; e < 4; e++) acc[mt][nt][e] = 0.f;

    float4 pe[4], be[4];
    #pragma unroll
    for (int t = 0; t < 4; t++) {
        int idx = t * 256 + tid;
        pe[t] = *(const float4*)(Eb + (size_t)(i0 + (idx >> 3)) * L_ + (idx & 7) * 4);
        be[t] = *(const float4*)(Bb + (size_t)(idx >> 5) * D_ + d0 + (idx & 31) * 4);
    }

    for (int c = 0; c < 64; c++) {
        const int buf = c & 1;
        float* P_ = Ps + buf * PBUF;
        float* B_ = Bs + buf * NBUF;
        #pragma unroll
        for (int t = 0; t < 4; t++) {
            int idx = t * 256 + tid;
            int prow = idx >> 3, pch = idx & 7;
            float m = rm_s[prow], siv = ri_s[prow];
            float4 p = make_float4(__expf(pe[t].x - m) * siv, __expf(pe[t].y - m) * siv,
                                   __expf(pe[t].z - m) * siv, __expf(pe[t].w - m) * siv);
            *(float4*)(P_ + prow * PPAD + pch * 4) = p;
            int brow = idx >> 5, bch = idx & 31;
            *(float4*)(B_ + brow * NPAD + bch * 4) = be[t];
        }
        __syncthreads();
        if (c + 1 < 64) {
            const int j0n = (c + 1) * 32;
            #pragma unroll
            for (int t = 0; t < 4; t++) {
                int idx = t * 256 + tid;
                pe[t] = *(const float4*)(Eb + (size_t)(i0 + (idx >> 3)) * L_ + j0n + (idx & 7) * 4);
                be[t] = *(const float4*)(Bb + (size_t)(j0n + (idx >> 5)) * D_ + d0 + (idx & 31) * 4);
            }
        }
        #pragma unroll
        for (int ks = 0; ks < 4; ks++) {
            const int kb = ks * 8;
            uint32_t pa[2][4], bh[8][2], bl[8][2];
            #pragma unroll
            for (int mt = 0; mt < 2; mt++) {
                const int rb = wm * 32 + mt * 16;
                pa[mt][0] = cvt_tf32(P_[(rb + q) * PPAD + kb + r]);
                pa[mt][1] = cvt_tf32(P_[(rb + q + 8) * PPAD + kb + r]);
                pa[mt][2] = cvt_tf32(P_[(rb + q) * PPAD + kb + r + 4]);
                pa[mt][3] = cvt_tf32(P_[(rb + q + 8) * PPAD + kb + r + 4]);
            }
            #pragma unroll
            for (int nt = 0; nt < 8; nt++) {
                const int nb = wn * 64 + nt * 8;
                split_tf32(B_[(kb + r) * NPAD + nb + q], bh[nt][0], bl[nt][0]);
                split_tf32(B_[(kb + r + 4) * NPAD + nb + q], bh[nt][1], bl[nt][1]);
            }
            #pragma unroll
            for (int mt = 0; mt < 2; mt++)
                #pragma unroll
                for (int nt = 0; nt < 8; nt++) {
                    mma8(acc[mt][nt], pa[mt], bl[nt]);
                    mma8(acc[mt][nt], pa[mt], bh[nt]);
                }
        }
        __syncthreads();
    }

    float* Ob = out + ((size_t)b * L_ + i0) * D_ + d0;
    #pragma unroll
    for (int mt = 0; mt < 2; mt++)
        #pragma unroll
        for (int nt = 0; nt < 8; nt++) {
            int row = wm * 32 + mt * 16 + q;
            int col = wn * 64 + nt * 8 + r * 2;
            *(float2*)(Ob + (size_t)row * D_ + col) =
                make_float2(acc[mt][nt][0], acc[mt][nt][1]);
            *(float2*)(Ob + (size_t)(row + 8) * D_ + col) =
                make_float2(acc[mt][nt][2], acc[mt][nt][3]);
        }
}

// ---------------------------------------------------------------------------
// b_tilda[j,d] = sum_i Q[i,j] * A[i,d].  M=j, N=d, K=i.
// Qs[32][136] ([k=i][m=j], exp applied), As2[32][136] ([k=i][n=d] raw).
// Q single tf32; A split hi/lo.
// ---------------------------------------------------------------------------
__global__ __launch_bounds__(256, 1) void k_btilda(const float* __restrict__ A,
                                                   float* __restrict__ out) {
    extern __shared__ float sm[];
    float* Qs = sm;                        // 2 * NBUF
    float* As2 = sm + 2 * NBUF;            // 2 * NBUF
    float* cm_s = sm + 4 * NBUF;
    float* ci_s = cm_s + 128;
    const int tid = threadIdx.x, lane = tid & 31, wid = tid >> 5;
    const int wm = wid & 3, wn = wid >> 2;
    const int q = lane >> 2, r = lane & 3;
    const int b = blockIdx.z, j0 = blockIdx.y * 128, d0 = blockIdx.x * 128;
    const float* Eb = g_E + (size_t)b * L_ * L_;
    const float* Ab = A + (size_t)b * L_ * D_;

    if (tid < 128) {
        cm_s[tid] = g_cmax[b * L_ + j0 + tid];
        ci_s[tid] = g_csumInv[b * L_ + j0 + tid];
    }
    __syncthreads();

    float acc[2][8][4];
    #pragma unroll
    for (int mt = 0; mt < 2; mt++)
        #pragma unroll
        for (int nt = 0; nt < 8; nt++)
            #pragma unroll
            for (int e = 0; e < 4; e++) acc[mt][nt][e] = 0.f;

    float4 qe[4], ae[4];
    #pragma unroll
    for (int t = 0; t < 4; t++) {
        int idx = t * 256 + tid;
        int irow = idx >> 5, ch = idx & 31;
        qe[t] = *(const float4*)(Eb + (size_t)irow * L_ + j0 + ch * 4);
        ae[t] = *(const float4*)(Ab + (size_t)irow * D_ + d0 + ch * 4);
    }

    for (int c = 0; c < 64; c++) {
        const int buf = c & 1;
        float* Q_ = Qs + buf * NBUF;
        float* A_ = As2 + buf * NBUF;
        #pragma unroll
        for (int t = 0; t < 4; t++) {
            int idx = t * 256 + tid;
            int irow = idx >> 5, ch = idx & 31;
            int jj = ch * 4;
            float4 p = make_float4(__expf(qe[t].x - cm_s[jj]) * ci_s[jj],
                                   __expf(qe[t].y - cm_s[jj + 1]) * ci_s[jj + 1],
                                   __expf(qe[t].z - cm_s[jj + 2]) * ci_s[jj + 2],
                                   __expf(qe[t].w - cm_s[jj + 3]) * ci_s[jj + 3]);
            *(float4*)(Q_ + irow * NPAD + jj) = p;
            *(float4*)(A_ + irow * NPAD + ch * 4) = ae[t];
        }
        __syncthreads();
        if (c + 1 < 64) {
            const int i0n = (c + 1) * 32;
            #pragma unroll
            for (int t = 0; t < 4; t++) {
                int idx = t * 256 + tid;
                int irow = idx >> 5, ch = idx & 31;
                qe[t] = *(const float4*)(Eb + (size_t)(i0n + irow) * L_ + j0 + ch * 4);
                ae[t] = *(const float4*)(Ab + (size_t)(i0n + irow) * D_ + d0 + ch * 4);
            }
        }
        #pragma unroll
        for (int ks = 0; ks < 4; ks++) {
            const int kb = ks * 8;
            uint32_t qa[2][4], bh[8][2], bl[8][2];
            #pragma unroll
            for (int mt = 0; mt < 2; mt++) {
                const int mb = wm * 32 + mt * 16;
                qa[mt][0] = cvt_tf32(Q_[(kb + r) * NPAD + mb + q]);
                qa[mt][1] = cvt_tf32(Q_[(kb + r) * NPAD + mb + q + 8]);
                qa[mt][2] = cvt_tf32(Q_[(kb + r + 4) * NPAD + mb + q]);
                qa[mt][3] = cvt_tf32(Q_[(kb + r + 4) * NPAD + mb + q + 8]);
            }
            #pragma unroll
            for (int nt = 0; nt < 8; nt++) {
                const int nb = wn * 64 + nt * 8;
                split_tf32(A_[(kb + r) * NPAD + nb + q], bh[nt][0], bl[nt][0]);
                split_tf32(A_[(kb + r + 4) * NPAD + nb + q], bh[nt][1], bl[nt][1]);
            }
            #pragma unroll
            for (int mt = 0; mt < 2; mt++)
                #pragma unroll
                for (int nt = 0; nt < 8; nt++) {
                    mma8(acc[mt][nt], qa[mt], bl[nt]);
                    mma8(acc[mt][nt], qa[mt], bh[nt]);
                }
        }
        __syncthreads();
    }

    float* Ob = out + ((size_t)b * L_ + j0) * D_ + d0;
    #pragma unroll
    for (int mt = 0; mt < 2; mt++)
        #pragma unroll
        for (int nt = 0; nt < 8; nt++) {
            int row = wm * 32 + mt * 16 + q;
            int col = wn * 64 + nt * 8 + r * 2;
            *(float2*)(Ob + (size_t)row * D_ + col) =
                make_float2(acc[mt][nt][0], acc[mt][nt][1]);
            *(float2*)(Ob + (size_t)(row + 8) * D_ + col) =
                make_float2(acc[mt][nt][2], acc[mt][nt][3]);
        }
}

// ---------------------------------------------------------------------------
extern "C" void kernel_launch(void* const* d_in, const int* in_sizes, int n_in,
                              void* d_out, int out_size) {
    const float* A = (const float*)d_in[0];
    const float* B = (const float*)d_in[1];
    float* out = (float*)d_out;
    float* a_tilda = out;
    float* b_tilda = out + (size_t)BN_ * L_ * D_;

    const int SMEM_E = 4 * EBUF * 4;                       // 73728 B
    const int SMEM_A = (2 * PBUF + 2 * NBUF + 256) * 4;    // 72704 B
    const int SMEM_B = (4 * NBUF + 256) * 4;               // 70656 B
    cudaFuncSetAttribute(k_gemm_e, cudaFuncAttributeMaxDynamicSharedMemorySize, SMEM_E);
    cudaFuncSetAttribute(k_atilda, cudaFuncAttributeMaxDynamicSharedMemorySize, SMEM_A);
    cudaFuncSetAttribute(k_btilda, cudaFuncAttributeMaxDynamicSharedMemorySize, SMEM_B);

    k_gemm_e<<<dim3(L_ / 128, L_ / 128, BN_), 256, SMEM_E>>>(A, B);
    k_rowstats<<<dim3(L_, BN_), 256>>>();
    k_colstats<<<dim3(L_ / 32, BN_), 256>>>();
    k_atilda<<<dim3(D_ / 128, L_ / 128, BN_), 256, SMEM_A>>>(B, a_tilda);
    k_btilda<<<dim3(D_ / 128, L_ / 128, BN_), 256, SMEM_B>>>(A, b_tilda);
}